// round 1
// baseline (speedup 1.0000x reference)
#include <cuda_runtime.h>

#define TILE_B   16
#define THREADS  256
#define NB       8192
#define NIO      64

// Precomputed per-(o,i) coefficient tables, laid out [i][o] for coalesced
// per-o lane reads.  A = {c1', b2', b3', b4}, B = {c5..c8} (gamma/64 folded).
__device__ float4 g_tabA[NIO * NIO];
__device__ float4 g_tabB[NIO * NIO];

__device__ __forceinline__ float ex2f_(float x) {
    float y; asm("ex2.approx.ftz.f32 %0, %1;" : "=f"(y) : "f"(x)); return y;
}
__device__ __forceinline__ float lg2f_(float x) {
    float y; asm("lg2.approx.ftz.f32 %0, %1;" : "=f"(y) : "f"(x)); return y;
}

// ---------------------------------------------------------------------------
// Setup: evaluate the 8 cubic splines at w_norm for every (o,i) pair and fold
// all constant factors so the main loop is pure EX2/LG2 + FFMA.
//   contribution = c1'*lg2(1 + b2'*lg2(1+p)) + x*(c5 + c6 x + c7 x^2 + c8 x^3)
//   where p = ex2(b4 * lg2(ex2(b3'*x) - 1))
// ---------------------------------------------------------------------------
__global__ void setup_kernel(const float* __restrict__ raw_gamma,
                             const float* __restrict__ w,
                             const float* __restrict__ breaks,
                             const float* __restrict__ coefs,
                             const float* __restrict__ mu_p,
                             const float* __restrict__ sig_p)
{
    int tid = blockIdx.x * blockDim.x + threadIdx.x;
    if (tid >= NIO * NIO) return;
    int o = tid >> 6;
    int i = tid & 63;

    float mu  = *mu_p;
    float sig = *sig_p;
    float wv  = w[tid];                       // w[o][i]
    float wc  = fminf(fmaxf(wv, -5.5f), 37.9f);
    float wn  = (wc - mu) / sig;

    float b[8];
#pragma unroll
    for (int s = 0; s < 8; s++) {
        const float* br = breaks + s * 20;
        float blo = br[0];
        float bhi = br[19] - 1e-6f;
        float wl  = fminf(fmaxf(wn, blo), bhi);
        int cnt = 0;
#pragma unroll
        for (int k = 0; k < 20; k++) cnt += (br[k] < wl) ? 1 : 0;
        int idx = cnt - 1;
        idx = max(idx, 0);
        idx = min(idx, 18);
        const float* a = coefs + (s * 19 + idx) * 4;
        float t = wl - br[idx];
        b[s] = ((a[0] * t + a[1]) * t + a[2]) * t + a[3];
    }

    float rg = raw_gamma[tid];
    float g  = (rg > 20.f) ? rg : log1pf(expf(rg));   // softplus
    float scale = g * (1.0f / 64.0f);

    const float LN2   = 0.6931471805599453f;
    const float LOG2E = 1.4426950408889634f;

    float4 A, Bq;
    A.x = b[0] * scale * LN2;   // c1'
    A.y = b[1] * LN2;           // b2'
    A.z = b[2] * LOG2E;         // b3'
    A.w = b[3];                 // b4
    Bq.x = b[4] * scale;
    Bq.y = b[5] * scale;
    Bq.z = b[6] * scale;
    Bq.w = b[7] * scale;

    int p = i * NIO + o;        // [i][o] layout
    g_tabA[p] = A;
    g_tabB[p] = Bq;
}

// ---------------------------------------------------------------------------
// Main kernel.  Block = 256 threads = 8 warps, TILE_B=16 batch rows per block.
// Warp -> (o-half, row subset).  Lanes are outputs, so x is warp-uniform and
// the relu-zero skip is done with divergence-free 64-bit mask iteration.
// ---------------------------------------------------------------------------
__global__ __launch_bounds__(THREADS)
void main_kernel(const float* __restrict__ x, float* __restrict__ out)
{
    __shared__ float    xs[TILE_B * 64];
    __shared__ unsigned mlo[TILE_B];
    __shared__ unsigned mhi[TILE_B];

    const int tid  = threadIdx.x;
    const long base = (long)blockIdx.x * TILE_B * 64;

    // Phase 1: load x tile + relu (coalesced)
#pragma unroll
    for (int idx = tid; idx < TILE_B * 64; idx += THREADS)
        xs[idx] = fmaxf(x[base + idx], 0.f);
    __syncthreads();

    const int lane = tid & 31;
    const int wp   = tid >> 5;

    // Phase 2: per-row 64-bit activity masks via ballot (warp wp -> rows 2wp, 2wp+1)
#pragma unroll
    for (int rr = 0; rr < 2; rr++) {
        int r = wp * 2 + rr;
        unsigned b0 = __ballot_sync(0xffffffffu, xs[r * 64 + lane]      > 0.f);
        unsigned b1 = __ballot_sync(0xffffffffu, xs[r * 64 + 32 + lane] > 0.f);
        if (lane == 0) { mlo[r] = b0; mhi[r] = b1; }
    }
    __syncthreads();

    // Phase 3: main loop.  warp -> o-half (wp&1), row stride 4 (wp>>1).
    const int o = lane + (wp & 1) * 32;

    for (int r = wp >> 1; r < TILE_B; r += 4) {
        float acc = 0.f;
        const float* xrow = xs + r * 64;
        unsigned lo = mlo[r];
        unsigned hi = mhi[r];

#define STEP(I)                                                           \
        {                                                                 \
            int ii = (I);                                                 \
            float xv = xrow[ii];              /* uniform broadcast */     \
            float4 A  = __ldg(&g_tabA[ii * NIO + o]);                     \
            float4 Bq = __ldg(&g_tabB[ii * NIO + o]);                     \
            float e  = ex2f_(A.z * xv) - 1.f;                             \
            float p  = ex2f_(A.w * lg2f_(e));                             \
            float l1 = lg2f_(1.f + p);                                    \
            float l2 = lg2f_(fmaf(A.y, l1, 1.f));                         \
            acc = fmaf(A.x, l2, acc);                                     \
            float x2 = xv * xv;                                           \
            float pA = fmaf(Bq.z, x2, Bq.x);  /* c5 + c7 x^2 */           \
            float pB = fmaf(Bq.w, x2, Bq.y);  /* c6 + c8 x^2 */           \
            acc = fmaf(fmaf(pB, xv, pA), xv, acc);                        \
        }

        while (lo) { int i = __ffs(lo) - 1;      lo &= lo - 1; STEP(i); }
        while (hi) { int i = (__ffs(hi) - 1)+32; hi &= hi - 1; STEP(i); }
#undef STEP

        out[((long)blockIdx.x * TILE_B + r) * 64 + o] = acc;
    }
}

// ---------------------------------------------------------------------------
extern "C" void kernel_launch(void* const* d_in, const int* in_sizes, int n_in,
                              void* d_out, int out_size)
{
    const float* x   = (const float*)d_in[0];
    const float* rg  = (const float*)d_in[1];
    const float* w   = (const float*)d_in[2];
    const float* br  = (const float*)d_in[3];
    const float* cf  = (const float*)d_in[4];
    const float* mu  = (const float*)d_in[5];
    const float* sg  = (const float*)d_in[6];
    float* out = (float*)d_out;

    setup_kernel<<<(NIO * NIO + 255) / 256, 256>>>(rg, w, br, cf, mu, sg);
    main_kernel<<<NB / TILE_B, THREADS>>>(x, out);
}